// round 1
// baseline (speedup 1.0000x reference)
#include <cuda_runtime.h>

#define NB 64       // batch
#define NT 512      // seq len
#define NE 256      // embed dim
#define NH 256      // hidden
#define NGATE 1024  // 4*NH
#define NK 9        // tags
#define NCTA 128    // persistent LSTM grid

// ---------------- scratch (__device__ globals; no allocation APIs) ----------
__device__ float d_gx[(size_t)2 * NT * NGATE * NB];     // [dir][t][gate][b]  256 MB
__device__ float d_hs[(size_t)2 * NT * NH * NB];        // [dir][t][j][b]     64 MB
__device__ float d_feats[(size_t)NB * NT * 2 * NH];     // [b][t][2H]         67 MB
__device__ float d_em[(size_t)NB * NT * NK];            // [b][t][k]
__device__ int d_preds[NB * NT];
__device__ float d_loss_partial[NB];
__device__ float d_loss;
__device__ unsigned int d_bar;

__global__ void k_init() { d_bar = 0u; }

// ---------------- input projection: gx[dir][t][g][b] = W_ih[g]·emb + b ------
__global__ __launch_bounds__(256) void k_gx(
    const int* __restrict__ widx, const int* __restrict__ lens,
    const float* __restrict__ wvec,
    const float* __restrict__ Wih_f, const float* __restrict__ b_f,
    const float* __restrict__ Wih_b, const float* __restrict__ b_b)
{
    __shared__ float sW[128 * 33];
    __shared__ float sX[64 * 33];
    __shared__ int rowidx[64];
    const int t = blockIdx.y;
    const int dir = blockIdx.z;
    const int g0 = blockIdx.x * 128;
    const float* Wih = dir ? Wih_b : Wih_f;
    const float* bias = dir ? b_b : b_f;
    const int tid = threadIdx.x;
    if (tid < 64) {
        int len = lens[tid];
        int tt = t;
        if (dir) tt = (t < len) ? (len - 1 - t) : t;  // reversed sequence
        rowidx[tid] = widx[tid * NT + tt];            // fused embedding gather
    }
    const int bg = tid & 15;   // batch group (4 batches)
    const int gg = tid >> 4;   // gate-row group (8 rows)
    float acc[8][4];
#pragma unroll
    for (int u = 0; u < 8; u++) {
        float bv = bias[g0 + gg * 8 + u];
#pragma unroll
        for (int v = 0; v < 4; v++) acc[u][v] = bv;
    }
    for (int e0 = 0; e0 < NE; e0 += 32) {
        __syncthreads();
#pragma unroll
        for (int i = 0; i < 16; i++) {
            int idx = tid + i * 256;
            int r = idx >> 5, c = idx & 31;
            sW[r * 33 + c] = Wih[(size_t)(g0 + r) * NE + e0 + c];
        }
#pragma unroll
        for (int i = 0; i < 8; i++) {
            int idx = tid + i * 256;
            int r = idx >> 5, c = idx & 31;
            sX[r * 33 + c] = wvec[(size_t)rowidx[r] * NE + e0 + c];
        }
        __syncthreads();
#pragma unroll
        for (int kk = 0; kk < 32; kk++) {
            float xv[4], wv[8];
#pragma unroll
            for (int v = 0; v < 4; v++) xv[v] = sX[(bg * 4 + v) * 33 + kk];
#pragma unroll
            for (int u = 0; u < 8; u++) wv[u] = sW[(gg * 8 + u) * 33 + kk];
#pragma unroll
            for (int u = 0; u < 8; u++)
#pragma unroll
                for (int v = 0; v < 4; v++) acc[u][v] += wv[u] * xv[v];
        }
    }
    float* gout = d_gx + ((size_t)(dir * NT + t) * NGATE + g0) * NB;
#pragma unroll
    for (int u = 0; u < 8; u++) {
        float4 val = make_float4(acc[u][0], acc[u][1], acc[u][2], acc[u][3]);
        *(float4*)(gout + (gg * 8 + u) * NB + bg * 4) = val;
    }
}

// ---------------- persistent bidirectional LSTM recurrence ------------------
// 128 CTAs (both dirs in one launch), grid-wide software barrier per step.
#define LSTM_SMEM_FLOATS (16 * 256 + 256 * 64 + 16 * 64)
__global__ __launch_bounds__(256, 1) void k_lstm(
    const float* __restrict__ Whh_f, const float* __restrict__ Whh_b)
{
    extern __shared__ float smem[];
    float* Ws = smem;                  // [16 gate-rows][256]
    float* h_sm = smem + 16 * 256;     // h_prev transposed [k][b] = [256][64]
    float* g_sm = h_sm + 256 * 64;     // gate exchange [16][64]
    const int tid = threadIdx.x;
    const int dir = blockIdx.x >> 6;
    const int j0 = (blockIdx.x & 63) * 4;   // 4 hidden units per CTA
    const float* Whh = dir ? Whh_b : Whh_f;
#pragma unroll
    for (int i = 0; i < 16; i++) {          // load W_hh slice once
        int idx = tid + i * 256;
        int rl = idx >> 8, k = idx & 255;
        int q = rl >> 2, jj = rl & 3;
        Ws[rl * 256 + k] = Whh[(size_t)(q * NH + j0 + jj) * NH + k];
    }
    const int rloc = tid >> 4, b4 = tid & 15;
    const int q = rloc >> 2, jj = rloc & 3;
    const int grow = q * NH + j0 + jj;
    const int jf = tid >> 6, bf = tid & 63;
    float c_reg = 0.f;
    unsigned bar_target = 0u;
    const float* wrow = Ws + rloc * 256;
    for (int t = 0; t < NT; t++) {
        float4* hdst = (float4*)h_sm;
        if (t == 0) {
            float4 z = make_float4(0.f, 0.f, 0.f, 0.f);
            for (int i = tid; i < NH * NB / 4; i += 256) hdst[i] = z;
        } else {
            const float4* hsrc =
                (const float4*)(d_hs + (size_t)(dir * NT + t - 1) * NH * NB);
            for (int i = tid; i < NH * NB / 4; i += 256) hdst[i] = __ldcg(hsrc + i);
        }
        __syncthreads();
        const float* gx = d_gx + (size_t)(dir * NT + t) * NGATE * NB;
        float4 a4 = *(const float4*)(gx + (size_t)grow * NB + b4 * 4);
        float a0 = a4.x, a1 = a4.y, a2 = a4.z, a3 = a4.w;
        const float* hb = h_sm + b4 * 4;
#pragma unroll 8
        for (int k = 0; k < 256; k++) {
            float w = wrow[k];
            float4 h4 = *(const float4*)(hb + k * 64);
            a0 += w * h4.x; a1 += w * h4.y; a2 += w * h4.z; a3 += w * h4.w;
        }
        *(float4*)(g_sm + rloc * 64 + b4 * 4) = make_float4(a0, a1, a2, a3);
        __syncthreads();
        // finalize: thread (jf, bf) owns hidden unit j0+jf, batch bf
        float gi = g_sm[jf * 64 + bf];
        float gfv = g_sm[(4 + jf) * 64 + bf];
        float gc = g_sm[(8 + jf) * 64 + bf];
        float go = g_sm[(12 + jf) * 64 + bf];
        float si = 1.f / (1.f + __expf(-gi));
        float sf = 1.f / (1.f + __expf(-gfv));
        float so = 1.f / (1.f + __expf(-go));
        c_reg = sf * c_reg + si * tanhf(gc);
        float h = so * tanhf(c_reg);
        d_hs[(size_t)((dir * NT + t) * NH + j0 + jf) * NB + bf] = h;
        __threadfence();
        __syncthreads();
        if (tid == 0) {                      // grid-wide barrier
            atomicAdd(&d_bar, 1u);
            bar_target += NCTA;
            while (*((volatile unsigned*)&d_bar) < bar_target) __nanosleep(32);
        }
        __syncthreads();
    }
}

// ---------------- feats: [b][t][2H] = mask * [h_fwd | h_bwd(unreversed)] ----
__global__ __launch_bounds__(256) void k_feats(const int* __restrict__ lens)
{
    __shared__ float tile[64][65];
    __shared__ int slen[64];
    const int ts = blockIdx.x;          // SOURCE time (keeps writes coalesced)
    const int j0 = blockIdx.y * 64;
    const int dir = blockIdx.z;
    const int tid = threadIdx.x;
    if (tid < 64) slen[tid] = lens[tid];
    const int b = tid & 63, jl = tid >> 6;
    const float* hsrc = d_hs + (size_t)((dir * NT + ts) * NH + j0) * NB;
#pragma unroll
    for (int i = 0; i < 16; i++)
        tile[jl + i * 4][b] = hsrc[(jl + i * 4) * NB + b];
    __syncthreads();
    const int jj = tid & 63, br = tid >> 6;
#pragma unroll
    for (int i = 0; i < 16; i++) {
        int bb = br * 16 + i;
        int len = slen[bb];
        bool valid = ts < len;
        int tout = dir ? (valid ? (len - 1 - ts) : ts) : ts;
        float v = valid ? tile[jj][bb] : 0.f;
        d_feats[(size_t)(bb * NT + tout) * (2 * NH) + dir * NH + j0 + jj] = v;
    }
}

// ---------------- emissions = feats @ W_out^T + b_out -----------------------
__global__ __launch_bounds__(256) void k_emis(const float* __restrict__ Wout,
                                              const float* __restrict__ bout)
{
    __shared__ float sW[NK * 512];
    const int tid = threadIdx.x;
    for (int i = tid; i < NK * 512; i += 256) sW[i] = Wout[i];
    __syncthreads();
    const int lane = tid & 31, warp = tid >> 5;
    const size_t bt = (size_t)blockIdx.x * 8 + warp;
    const float* f = d_feats + bt * 512;
    float x[16];
#pragma unroll
    for (int i = 0; i < 16; i++) x[i] = f[lane + i * 32];
#pragma unroll
    for (int k = 0; k < NK; k++) {
        float acc = 0.f;
#pragma unroll
        for (int i = 0; i < 16; i++) acc += x[i] * sW[k * 512 + lane + i * 32];
#pragma unroll
        for (int off = 16; off; off >>= 1)
            acc += __shfl_xor_sync(0xffffffffu, acc, off);
        if (lane == 0) d_em[bt * NK + k] = acc + bout[k];
    }
}

// ---------------- CRF: numerator + alpha (logZ) + Viterbi + backtrace -------
__global__ void k_crf(const int* __restrict__ lens, const int* __restrict__ labels,
                      const float* __restrict__ stt, const float* __restrict__ ett,
                      const float* __restrict__ trans)
{
    __shared__ unsigned char hist[NT][NK];
    const int b = blockIdx.x;
    const int lane = threadIdx.x;
    const int len = lens[b];
    const float* em = d_em + (size_t)b * NT * NK;
    const int* lab = labels + b * NT;
    const int j = (lane < NK) ? lane : 0;
    float tr[NK];
#pragma unroll
    for (int i = 0; i < NK; i++) tr[i] = trans[i * NK + j];
    float sA = stt[j] + em[j];
    float sV = sA;
    int yprev = lab[0];
    float num = stt[yprev] + em[yprev];
    for (int t = 1; t < NT; t++) {
        float e = em[t * NK + j];
        bool m = t < len;
        float aA[NK], aV[NK];
#pragma unroll
        for (int i = 0; i < NK; i++) {
            aA[i] = __shfl_sync(0xffffffffu, sA, i) + tr[i];
            aV[i] = __shfl_sync(0xffffffffu, sV, i) + tr[i];
        }
        float mA = aA[0];
#pragma unroll
        for (int i = 1; i < NK; i++) mA = fmaxf(mA, aA[i]);
        float ssum = 0.f;
#pragma unroll
        for (int i = 0; i < NK; i++) ssum += __expf(aA[i] - mA);
        float nA = mA + __logf(ssum) + e;
        float mV = aV[0]; int bp = 0;
#pragma unroll
        for (int i = 1; i < NK; i++) { if (aV[i] > mV) { mV = aV[i]; bp = i; } }
        float nV = mV + e;
        if (lane < NK) hist[t][lane] = (unsigned char)bp;
        if (m) { sA = nA; sV = nV; }
        if (lane == 0) {
            int y = lab[t];
            if (m) num += trans[yprev * NK + y] + em[t * NK + y];
            yprev = y;
        }
    }
    float fA = sA + ett[j];
    float fV = sV + ett[j];
    float gA[NK], gV[NK];
#pragma unroll
    for (int i = 0; i < NK; i++) {
        gA[i] = __shfl_sync(0xffffffffu, fA, i);
        gV[i] = __shfl_sync(0xffffffffu, fV, i);
    }
    __syncwarp();
    if (lane == 0) {
        float mA = gA[0];
#pragma unroll
        for (int i = 1; i < NK; i++) mA = fmaxf(mA, gA[i]);
        float ssum = 0.f;
#pragma unroll
        for (int i = 0; i < NK; i++) ssum += __expf(gA[i] - mA);
        float denom = mA + __logf(ssum);
        int bl = 0; float mV = gV[0];
#pragma unroll
        for (int i = 1; i < NK; i++) { if (gV[i] > mV) { mV = gV[i]; bl = i; } }
        num += ett[lab[len - 1]];
        d_loss_partial[b] = num - denom;
        int cur = bl;
        d_preds[b * NT + NT - 1] = (NT - 1 < len) ? cur : 0;
        for (int t = NT - 2; t >= 0; t--) {
            if (t + 1 < len) cur = (int)hist[t + 1][cur];
            d_preds[b * NT + t] = (t < len) ? cur : 0;
        }
    }
}

__global__ void k_loss() {
    float s = 0.f;
    for (int i = 0; i < NB; i++) s += d_loss_partial[i];
    d_loss = -s / (float)NB;
}

// output layout: [loss(1), preds(B*T), feats(B*T*2H)] as float32, prefix-safe.
__global__ void k_writeout(float* __restrict__ out, int n) {
    int i = blockIdx.x * 256 + threadIdx.x;
    if (i >= n) return;
    float v = 0.f;
    if (i == 0) v = d_loss;
    else if (i < 1 + NB * NT) v = (float)d_preds[i - 1];
    else if (i < 1 + NB * NT + NB * NT * 2 * NH) v = d_feats[i - 1 - NB * NT];
    out[i] = v;
}

extern "C" void kernel_launch(void* const* d_in, const int* in_sizes, int n_in,
                              void* d_out, int out_size) {
    const int* widx = (const int*)d_in[0];
    const int* lens = (const int*)d_in[1];
    const int* labels = (const int*)d_in[2];
    const float* wvec = (const float*)d_in[3];
    const float* Wih_f = (const float*)d_in[4];
    const float* Whh_f = (const float*)d_in[5];
    const float* b_f = (const float*)d_in[6];
    const float* Wih_b = (const float*)d_in[7];
    const float* Whh_b = (const float*)d_in[8];
    const float* b_b = (const float*)d_in[9];
    const float* Wout = (const float*)d_in[10];
    const float* bout = (const float*)d_in[11];
    const float* stt = (const float*)d_in[12];
    const float* ett = (const float*)d_in[13];
    const float* trans = (const float*)d_in[14];

    k_init<<<1, 1>>>();

    dim3 gg(NGATE / 128, NT, 2);
    k_gx<<<gg, 256>>>(widx, lens, wvec, Wih_f, b_f, Wih_b, b_b);

    int smem_bytes = LSTM_SMEM_FLOATS * 4;
    cudaFuncSetAttribute(k_lstm, cudaFuncAttributeMaxDynamicSharedMemorySize,
                         smem_bytes);
    k_lstm<<<NCTA, 256, smem_bytes>>>(Whh_f, Whh_b);

    dim3 gf(NT, NH / 64, 2);
    k_feats<<<gf, 256>>>(lens);

    k_emis<<<NB * NT / 8, 256>>>(Wout, bout);
    k_crf<<<NB, 32>>>(lens, labels, stt, ett, trans);
    k_loss<<<1, 1>>>();

    k_writeout<<<(out_size + 255) / 256, 256>>>((float*)d_out, out_size);
}

// round 2
// speedup vs baseline: 1.1458x; 1.1458x over previous
#include <cuda_runtime.h>

#define NB 64       // batch
#define NT 512      // seq len
#define NE 256      // embed dim
#define NH 256      // hidden
#define NGATE 1024  // 4*NH
#define NK 9        // tags
#define NCTA 128    // persistent LSTM grid (64 per direction)

typedef unsigned long long u64;

// ---------------- packed fp32x2 helpers (sm_103a FFMA2) ---------------------
__device__ __forceinline__ void fma2(u64& d, u64 a, u64 b) {
    asm("fma.rn.f32x2 %0, %1, %2, %0;" : "+l"(d) : "l"(a), "l"(b));
}
__device__ __forceinline__ u64 pk2(float x, float y) {
    u64 r; asm("mov.b64 %0, {%1,%2};" : "=l"(r) : "f"(x), "f"(y)); return r;
}
__device__ __forceinline__ unsigned smem_u32(const void* p) {
    return (unsigned)__cvta_generic_to_shared(p);
}
__device__ __forceinline__ void cp16(unsigned dst, const void* src) {
    asm volatile("cp.async.cg.shared.global [%0], [%1], 16;" :: "r"(dst), "l"(src));
}
__device__ __forceinline__ void cp_commit() {
    asm volatile("cp.async.commit_group;");
}

// ---------------- scratch (__device__ globals; no allocation APIs) ----------
__device__ float d_gx[(size_t)2 * NT * NGATE * NB];     // [dir][t][gate][b]
__device__ float d_hs[(size_t)2 * NT * NH * NB];        // [dir][t][j][b]
__device__ float d_feats[(size_t)NB * NT * 2 * NH];     // [b][t][2H]
__device__ float d_em[(size_t)NB * NT * NK];            // [b][t][k]
__device__ int d_preds[NB * NT];
__device__ float d_loss_partial[NB];
__device__ float d_loss;
__device__ unsigned int d_bar2[64];                     // [dir*32]: 128B apart

__global__ void k_init() {
    if (threadIdx.x < 64) d_bar2[threadIdx.x] = 0u;
}

// ---------------- input projection: gx[dir][t][g][b] = W_ih[g]·emb + b ------
__global__ __launch_bounds__(256) void k_gx(
    const int* __restrict__ widx, const int* __restrict__ lens,
    const float* __restrict__ wvec,
    const float* __restrict__ Wih_f, const float* __restrict__ b_f,
    const float* __restrict__ Wih_b, const float* __restrict__ b_b)
{
    __shared__ float4 sWd[64 * 32];       // [row-pair][col] dup: (w0,w0,w1,w1)
    __shared__ float sXT[32 * 66];        // [e][b], stride 66 (even, low-conflict)
    __shared__ int rowidx[64];
    const int t = blockIdx.y;
    const int dir = blockIdx.z;
    const int g0 = blockIdx.x * 128;
    const float* Wih = dir ? Wih_b : Wih_f;
    const float* bias = dir ? b_b : b_f;
    const int tid = threadIdx.x;
    if (tid < 64) {
        int len = lens[tid];
        int tt = t;
        if (dir) tt = (t < len) ? (len - 1 - t) : t;  // reversed sequence
        rowidx[tid] = widx[tid * NT + tt];            // fused embedding gather
    }
    const int bg = tid & 15;   // batch group (4 batches)
    const int gg = tid >> 4;   // gate-row group (8 rows)
    u64 acc[8][2];
#pragma unroll
    for (int u = 0; u < 8; u++) {
        float bv = bias[g0 + gg * 8 + u];
        acc[u][0] = pk2(bv, bv);
        acc[u][1] = acc[u][0];
    }
    for (int e0 = 0; e0 < NE; e0 += 32) {
        __syncthreads();
#pragma unroll
        for (int i = 0; i < 16; i++) {            // W slice, duplicated pairs
            int idx = tid + i * 256;
            int r = idx >> 5, c = idx & 31;
            float w = Wih[(size_t)(g0 + r) * NE + e0 + c];
            float* dst = (float*)&sWd[(r >> 1) * 32 + c];
            dst[(r & 1) * 2 + 0] = w;
            dst[(r & 1) * 2 + 1] = w;
        }
#pragma unroll
        for (int i = 0; i < 8; i++) {             // X transposed [e][b]
            int idx = tid + i * 256;
            int r = idx >> 5, c = idx & 31;
            sXT[c * 66 + r] = wvec[(size_t)rowidx[r] * NE + e0 + c];
        }
        __syncthreads();
#pragma unroll
        for (int kk = 0; kk < 32; kk++) {
            u64 x01 = *(const u64*)&sXT[kk * 66 + bg * 4];
            u64 x23 = *(const u64*)&sXT[kk * 66 + bg * 4 + 2];
#pragma unroll
            for (int up = 0; up < 4; up++) {
                ulonglong2 wq = *(const ulonglong2*)&sWd[(gg * 4 + up) * 32 + kk];
                fma2(acc[up * 2 + 0][0], wq.x, x01);
                fma2(acc[up * 2 + 0][1], wq.x, x23);
                fma2(acc[up * 2 + 1][0], wq.y, x01);
                fma2(acc[up * 2 + 1][1], wq.y, x23);
            }
        }
    }
    float* gout = d_gx + ((size_t)(dir * NT + t) * NGATE + g0) * NB;
#pragma unroll
    for (int u = 0; u < 8; u++) {
        *(u64*)(gout + (gg * 8 + u) * NB + bg * 4) = acc[u][0];
        *(u64*)(gout + (gg * 8 + u) * NB + bg * 4 + 2) = acc[u][1];
    }
}

// ---------------- persistent bidirectional LSTM recurrence ------------------
// 128 CTAs (64/dir), 128 threads, per-direction software barrier per step.
// smem: WsP 32KB (dup pairs) + h_sm 64KB + g_sm 4KB = 100KB
#define LSTM_SMEM_FLOATS (8 * 256 * 4 + 256 * 64 + 16 * 64)
__global__ __launch_bounds__(128, 1) void k_lstm(
    const float* __restrict__ Whh_f, const float* __restrict__ Whh_b)
{
    extern __shared__ float smem[];
    float4* WsP = (float4*)smem;            // [8 row-pairs][256 k]
    float* h_sm = smem + 8192;              // [k][b] = [256][64]
    float* g_sm = smem + 8192 + 16384;      // [16 rows][64]
    const int tid = threadIdx.x;
    const int dir = blockIdx.x >> 6;
    const int j0 = (blockIdx.x & 63) * 4;   // 4 hidden units per CTA
    const float* Whh = dir ? Whh_b : Whh_f;
#pragma unroll
    for (int i = 0; i < 16; i++) {          // load W_hh slice, duplicated pairs
        int idx = tid + i * 128;
        int rp = idx >> 8, k = idx & 255;
        int rl0 = rp * 2;
        int q = rl0 >> 2, jj = rl0 & 3;
        float w0 = Whh[(size_t)(q * NH + j0 + jj) * NH + k];
        float w1 = Whh[(size_t)(q * NH + j0 + jj + 1) * NH + k];
        WsP[rp * 256 + k] = make_float4(w0, w0, w1, w1);
    }
    const int bp = tid & 15;                // batch group (4 batches)
    const int rp = tid >> 4;                // row pair (rows 2rp, 2rp+1)
    const int rl0 = rp * 2;
    const int q = rl0 >> 2, jj0 = rl0 & 3;
    const int grow0 = q * NH + j0 + jj0;
    const int jA = tid >> 6, bA = tid & 63; // finalize: (jA,bA) and (jA+2,bA)
    float cA = 0.f, cB = 0.f;
    unsigned target = 0u;
    volatile unsigned* bar = &d_bar2[dir * 32];
    const unsigned h_b32 = smem_u32(h_sm);
    const ulonglong2* wp = (const ulonglong2*)(WsP + rp * 256);
    for (int t = 0; t < NT; t++) {
        const float* gx = d_gx + (size_t)(dir * NT + t) * NGATE * NB;
        u64 a00 = *(const u64*)(gx + (size_t)grow0 * NB + bp * 4);
        u64 a01 = *(const u64*)(gx + (size_t)grow0 * NB + bp * 4 + 2);
        u64 a10 = *(const u64*)(gx + (size_t)(grow0 + 1) * NB + bp * 4);
        u64 a11 = *(const u64*)(gx + (size_t)(grow0 + 1) * NB + bp * 4 + 2);
        if (t > 0) {
            const float4* hsrc =
                (const float4*)(d_hs + (size_t)(dir * NT + t - 1) * NH * NB);
            // chunked cp.async pipeline: 4 chunks of 64 k (1024 float4 each)
#pragma unroll
            for (int j = 0; j < 8; j++) {
                int i = j * 128 + tid;
                cp16(h_b32 + i * 16, hsrc + i);
            }
            cp_commit();
#pragma unroll
            for (int c = 0; c < 4; c++) {
                if (c < 3) {
#pragma unroll
                    for (int j = 0; j < 8; j++) {
                        int i = (c + 1) * 1024 + j * 128 + tid;
                        cp16(h_b32 + i * 16, hsrc + i);
                    }
                    cp_commit();
                    asm volatile("cp.async.wait_group 1;");
                } else {
                    asm volatile("cp.async.wait_group 0;");
                }
                __syncthreads();
                const int kbase = c * 64;
#pragma unroll 16
                for (int k = kbase; k < kbase + 64; k++) {
                    ulonglong2 w = wp[k];
                    ulonglong2 h = *(const ulonglong2*)(h_sm + k * 64 + bp * 4);
                    fma2(a00, w.x, h.x);
                    fma2(a01, w.x, h.y);
                    fma2(a10, w.y, h.x);
                    fma2(a11, w.y, h.y);
                }
            }
        }
        // gate exchange
        *(u64*)(g_sm + rl0 * 64 + bp * 4) = a00;
        *(u64*)(g_sm + rl0 * 64 + bp * 4 + 2) = a01;
        *(u64*)(g_sm + (rl0 + 1) * 64 + bp * 4) = a10;
        *(u64*)(g_sm + (rl0 + 1) * 64 + bp * 4 + 2) = a11;
        __syncthreads();
        // finalize two (hidden, batch) pairs per thread
        float* hout = d_hs + (size_t)((dir * NT + t) * NH + j0) * NB;
        {
            float gi = g_sm[jA * 64 + bA];
            float gf = g_sm[(4 + jA) * 64 + bA];
            float gc = g_sm[(8 + jA) * 64 + bA];
            float go = g_sm[(12 + jA) * 64 + bA];
            float si = 1.f / (1.f + __expf(-gi));
            float sf = 1.f / (1.f + __expf(-gf));
            float so = 1.f / (1.f + __expf(-go));
            cA = sf * cA + si * tanhf(gc);
            hout[jA * NB + bA] = so * tanhf(cA);
        }
        {
            int j2 = jA + 2;
            float gi = g_sm[j2 * 64 + bA];
            float gf = g_sm[(4 + j2) * 64 + bA];
            float gc = g_sm[(8 + j2) * 64 + bA];
            float go = g_sm[(12 + j2) * 64 + bA];
            float si = 1.f / (1.f + __expf(-gi));
            float sf = 1.f / (1.f + __expf(-gf));
            float so = 1.f / (1.f + __expf(-go));
            cB = sf * cB + si * tanhf(gc);
            hout[j2 * NB + bA] = so * tanhf(cB);
        }
        __threadfence();
        __syncthreads();
        if (t < NT - 1) {
            if (tid == 0) {                  // per-direction barrier (64 CTAs)
                atomicAdd((unsigned*)bar, 1u);
                target += 64u;
                while (*bar < target) __nanosleep(20);
            }
            __syncthreads();
        }
    }
}

// ---------------- feats: [b][t][2H] = mask * [h_fwd | h_bwd(unreversed)] ----
__global__ __launch_bounds__(256) void k_feats(const int* __restrict__ lens)
{
    __shared__ float tile[64][65];
    __shared__ int slen[64];
    const int ts = blockIdx.x;          // SOURCE time (keeps writes coalesced)
    const int j0 = blockIdx.y * 64;
    const int dir = blockIdx.z;
    const int tid = threadIdx.x;
    if (tid < 64) slen[tid] = lens[tid];
    const int b = tid & 63, jl = tid >> 6;
    const float* hsrc = d_hs + (size_t)((dir * NT + ts) * NH + j0) * NB;
#pragma unroll
    for (int i = 0; i < 16; i++)
        tile[jl + i * 4][b] = hsrc[(jl + i * 4) * NB + b];
    __syncthreads();
    const int jj = tid & 63, br = tid >> 6;
#pragma unroll
    for (int i = 0; i < 16; i++) {
        int bb = br * 16 + i;
        int len = slen[bb];
        bool valid = ts < len;
        int tout = dir ? (valid ? (len - 1 - ts) : ts) : ts;
        float v = valid ? tile[jj][bb] : 0.f;
        d_feats[(size_t)(bb * NT + tout) * (2 * NH) + dir * NH + j0 + jj] = v;
    }
}

// ---------------- emissions = feats @ W_out^T + b_out -----------------------
__global__ __launch_bounds__(256) void k_emis(const float* __restrict__ Wout,
                                              const float* __restrict__ bout)
{
    __shared__ float sW[NK * 512];
    const int tid = threadIdx.x;
    for (int i = tid; i < NK * 512; i += 256) sW[i] = Wout[i];
    __syncthreads();
    const int lane = tid & 31, warp = tid >> 5;
    const size_t bt = (size_t)blockIdx.x * 8 + warp;
    const float* f = d_feats + bt * 512;
    float x[16];
#pragma unroll
    for (int i = 0; i < 16; i++) x[i] = f[lane + i * 32];
#pragma unroll
    for (int k = 0; k < NK; k++) {
        float acc = 0.f;
#pragma unroll
        for (int i = 0; i < 16; i++) acc += x[i] * sW[k * 512 + lane + i * 32];
#pragma unroll
        for (int off = 16; off; off >>= 1)
            acc += __shfl_xor_sync(0xffffffffu, acc, off);
        if (lane == 0) d_em[bt * NK + k] = acc + bout[k];
    }
}

// ---------------- CRF: numerator + alpha (logZ) + Viterbi + backtrace -------
__global__ void k_crf(const int* __restrict__ lens, const int* __restrict__ labels,
                      const float* __restrict__ stt, const float* __restrict__ ett,
                      const float* __restrict__ trans)
{
    __shared__ unsigned char hist[NT][NK];
    const int b = blockIdx.x;
    const int lane = threadIdx.x;
    const int len = lens[b];
    const float* em = d_em + (size_t)b * NT * NK;
    const int* lab = labels + b * NT;
    const int j = (lane < NK) ? lane : 0;
    float tr[NK];
#pragma unroll
    for (int i = 0; i < NK; i++) tr[i] = trans[i * NK + j];
    float sA = stt[j] + em[j];
    float sV = sA;
    int yprev = lab[0];
    float num = stt[yprev] + em[yprev];
    for (int t = 1; t < NT; t++) {
        float e = em[t * NK + j];
        bool m = t < len;
        float aA[NK], aV[NK];
#pragma unroll
        for (int i = 0; i < NK; i++) {
            aA[i] = __shfl_sync(0xffffffffu, sA, i) + tr[i];
            aV[i] = __shfl_sync(0xffffffffu, sV, i) + tr[i];
        }
        float mA = aA[0];
#pragma unroll
        for (int i = 1; i < NK; i++) mA = fmaxf(mA, aA[i]);
        float ssum = 0.f;
#pragma unroll
        for (int i = 0; i < NK; i++) ssum += __expf(aA[i] - mA);
        float nA = mA + __logf(ssum) + e;
        float mV = aV[0]; int bp = 0;
#pragma unroll
        for (int i = 1; i < NK; i++) { if (aV[i] > mV) { mV = aV[i]; bp = i; } }
        float nV = mV + e;
        if (lane < NK) hist[t][lane] = (unsigned char)bp;
        if (m) { sA = nA; sV = nV; }
        if (lane == 0) {
            int y = lab[t];
            if (m) num += trans[yprev * NK + y] + em[t * NK + y];
            yprev = y;
        }
    }
    float fA = sA + ett[j];
    float fV = sV + ett[j];
    float gA[NK], gV[NK];
#pragma unroll
    for (int i = 0; i < NK; i++) {
        gA[i] = __shfl_sync(0xffffffffu, fA, i);
        gV[i] = __shfl_sync(0xffffffffu, fV, i);
    }
    __syncwarp();
    if (lane == 0) {
        float mA = gA[0];
#pragma unroll
        for (int i = 1; i < NK; i++) mA = fmaxf(mA, gA[i]);
        float ssum = 0.f;
#pragma unroll
        for (int i = 0; i < NK; i++) ssum += __expf(gA[i] - mA);
        float denom = mA + __logf(ssum);
        int bl = 0; float mV = gV[0];
#pragma unroll
        for (int i = 1; i < NK; i++) { if (gV[i] > mV) { mV = gV[i]; bl = i; } }
        num += ett[lab[len - 1]];
        d_loss_partial[b] = num - denom;
        int cur = bl;
        d_preds[b * NT + NT - 1] = (NT - 1 < len) ? cur : 0;
        for (int t = NT - 2; t >= 0; t--) {
            if (t + 1 < len) cur = (int)hist[t + 1][cur];
            d_preds[b * NT + t] = (t < len) ? cur : 0;
        }
    }
}

__global__ void k_loss() {
    float s = 0.f;
    for (int i = 0; i < NB; i++) s += d_loss_partial[i];
    d_loss = -s / (float)NB;
}

// output layout: [loss(1), preds(B*T), feats(B*T*2H)] as float32, prefix-safe.
__global__ void k_writeout(float* __restrict__ out, int n) {
    int i = blockIdx.x * 256 + threadIdx.x;
    if (i >= n) return;
    float v = 0.f;
    if (i == 0) v = d_loss;
    else if (i < 1 + NB * NT) v = (float)d_preds[i - 1];
    else if (i < 1 + NB * NT + NB * NT * 2 * NH) v = d_feats[i - 1 - NB * NT];
    out[i] = v;
}

extern "C" void kernel_launch(void* const* d_in, const int* in_sizes, int n_in,
                              void* d_out, int out_size) {
    const int* widx = (const int*)d_in[0];
    const int* lens = (const int*)d_in[1];
    const int* labels = (const int*)d_in[2];
    const float* wvec = (const float*)d_in[3];
    const float* Wih_f = (const float*)d_in[4];
    const float* Whh_f = (const float*)d_in[5];
    const float* b_f = (const float*)d_in[6];
    const float* Wih_b = (const float*)d_in[7];
    const float* Whh_b = (const float*)d_in[8];
    const float* b_b = (const float*)d_in[9];
    const float* Wout = (const float*)d_in[10];
    const float* bout = (const float*)d_in[11];
    const float* stt = (const float*)d_in[12];
    const float* ett = (const float*)d_in[13];
    const float* trans = (const float*)d_in[14];

    k_init<<<1, 64>>>();

    dim3 gg(NGATE / 128, NT, 2);
    k_gx<<<gg, 256>>>(widx, lens, wvec, Wih_f, b_f, Wih_b, b_b);

    int smem_bytes = LSTM_SMEM_FLOATS * 4;
    cudaFuncSetAttribute(k_lstm, cudaFuncAttributeMaxDynamicSharedMemorySize,
                         smem_bytes);
    k_lstm<<<NCTA, 128, smem_bytes>>>(Whh_f, Whh_b);

    dim3 gf(NT, NH / 64, 2);
    k_feats<<<gf, 256>>>(lens);

    k_emis<<<NB * NT / 8, 256>>>(Wout, bout);
    k_crf<<<NB, 32>>>(lens, labels, stt, ett, trans);
    k_loss<<<1, 1>>>();

    k_writeout<<<(out_size + 255) / 256, 256>>>((float*)d_out, out_size);
}